// round 9
// baseline (speedup 1.0000x reference)
#include <cuda_runtime.h>
#include <cuda_bf16.h>
#include <cstdint>

// Problem constants
#define B_ 4
#define C_ 64
#define T_ 8
#define X_ 96
#define Y_ 96
#define S_ 9216            // X_*Y_
#define N_ 36864           // B_*S_
#define TS_ 73728          // T_*S_
#define TOTAL_ 18874368    // B_*C_*T_*S_
#define QSZ_ 18874368      // T_*C_*N_
#define CNT_ 294912.0f     // B_*T_*S_

// -------- scratch (device globals; no runtime allocation) --------
__device__ float g_x[TOTAL_];                     // conv0 raw output (pre-BN0)
__device__ __nv_bfloat16 g_qkvh[3 * QSZ_];        // q,k,v bf16, [z][t][c][n]
__device__ __nv_bfloat16 g_oh[QSZ_];              // attention out bf16, [t][c][n]
__device__ __nv_bfloat16 g_zh[TOTAL_];            // residual + out_proj (pre-BN1), bf16
__device__ float g_sum0[128];
__device__ float g_sum1[128];
__device__ float g_coef0[128];                    // bn0: A[0:64], B[64:128]
__device__ float g_coef1[128];
__device__ float g_m[B_ * C_ * T_];
__device__ float g_kern[B_ * T_ * 25];
__device__ __align__(16) __nv_bfloat16 g_wk[64 * 576];   // conv0 [co][k], k=tap*64+ci
__device__ __align__(16) __nv_bfloat16 g_wqkv[192 * 64]; // in_proj bf16
__device__ __align__(16) __nv_bfloat16 g_wout[64 * 64];  // out_proj bf16

__device__ __forceinline__ float lk(float v) { return v >= 0.f ? v : 0.01f * v; }

__device__ __forceinline__ void mma_bf16(float* c, uint32_t a0, uint32_t a1,
                                         uint32_t a2, uint32_t a3,
                                         uint32_t b0, uint32_t b1) {
    asm volatile(
        "mma.sync.aligned.m16n8k16.row.col.f32.bf16.bf16.f32 "
        "{%0,%1,%2,%3}, {%4,%5,%6,%7}, {%8,%9}, {%0,%1,%2,%3};"
        : "+f"(c[0]), "+f"(c[1]), "+f"(c[2]), "+f"(c[3])
        : "r"(a0), "r"(a1), "r"(a2), "r"(a3), "r"(b0), "r"(b1));
}

__device__ __forceinline__ uint32_t packbf(float a, float b) {
    __nv_bfloat162 p = __floats2bfloat162_rn(a, b);
    return *(uint32_t*)&p;
}

// ===================== weight prep =====================
__global__ void k_wprep(const float* __restrict__ w) {
    int i = blockIdx.x * 256 + threadIdx.x;
    if (i >= 64 * 576) return;
    int co = i / 576, k = i - co * 576;
    int tap = k >> 6, ci = k & 63;
    g_wk[i] = __float2bfloat16(w[(co * 64 + ci) * 9 + tap]);
}
__global__ void k_wprep2(const float* __restrict__ inW, const float* __restrict__ outW) {
    int i = blockIdx.x * 256 + threadIdx.x;
    if (i < 192 * 64) g_wqkv[i] = __float2bfloat16(inW[i]);
    if (i < 64 * 64) g_wout[i] = __float2bfloat16(outW[i]);
}

// ===================== conv0: persistent tile-pair bf16 mma, 512 thr =====================
#define SINW 74
#define ROWE (98 * SINW)                // 7252 elems per row slot
#define RING 8
#define WKS 584
#define SM_WK_OFF (RING * ROWE * 2)     // 116032 bytes
#define SM_CONV_TOT (SM_WK_OFF + 64 * WKS * 2)   // 190784 bytes

__device__ __forceinline__ void stage_row(__nv_bfloat16* sin_s, const float* hb,
                                          int gx, int tid) {
    const int slot = (gx + 8) & 7;
    __nv_bfloat16* dst = sin_s + slot * ROWE;
    if ((unsigned)gx >= 96u) {
        for (int e = tid; e < 6144; e += 512) {
            int ci = e / 96, y = e - ci * 96;
            dst[(y + 1) * SINW + ci] = __float2bfloat16(0.f);
        }
    } else {
        const float* hp = hb + (size_t)gx * 96;
        for (int e = tid; e < 6144; e += 512) {
            int ci = e / 96, y = e - ci * 96;
            dst[(y + 1) * SINW + ci] = __float2bfloat16(hp[(size_t)ci * TS_ + y]);
        }
    }
    if (tid < 64) dst[tid] = __float2bfloat16(0.f);
    else if (tid < 128) dst[97 * SINW + (tid - 64)] = __float2bfloat16(0.f);
}

__global__ void __launch_bounds__(512)
k_conv0_mma(const float* __restrict__ h, const float* __restrict__ bias) {
    extern __shared__ char smem[];
    __nv_bfloat16* sin_s = (__nv_bfloat16*)smem;
    __nv_bfloat16* wk_s = (__nv_bfloat16*)(smem + SM_WK_OFF);
    __shared__ float s_st[128];

    const int tid = threadIdx.x, lane = tid & 31, wid = tid >> 5;
    const int group = blockIdx.x, bt = blockIdx.y, b = bt >> 3, t = bt & 7;
    const float* hb = h + (size_t)b * (64 * TS_) + (size_t)t * S_;

    if (tid < 128) s_st[tid] = 0.f;
    // stage weights once
    {
        const uint4* src = (const uint4*)g_wk;
        for (int e = tid; e < 4608; e += 512) {
            int co = e / 72, q = e - co * 72;
            *(uint4*)&wk_s[co * WKS + q * 8] = src[e];
        }
    }
    // prologue: rows for first tile-pair
    {
        const int p0 = group * 2304;
        const int xlo = p0 / 96, xhi = (p0 + 255) / 96;
        for (int gx = xlo - 1; gx <= xhi + 1; gx++) stage_row(sin_s, hb, gx, tid);
    }
    __syncthreads();

    const int mg = wid >> 1, nh = wid & 1;   // mg: 8 pixel groups of 32; nh: co half
    const int g = lane >> 2, tg = lane & 3;

    float bv[4][2];
#pragma unroll
    for (int nt = 0; nt < 4; nt++) {
        const int co0 = nh * 32 + nt * 8 + tg * 2;
        bv[nt][0] = __ldg(&bias[co0]);
        bv[nt][1] = __ldg(&bias[co0 + 1]);
    }

    float st_s[8], st_q[8];
#pragma unroll
    for (int i = 0; i < 8; i++) { st_s[i] = 0.f; st_q[i] = 0.f; }

    float* obB = g_x + (size_t)b * (64 * TS_) + (size_t)t * S_;

    for (int ti = 0; ti < 9; ti++) {
        const int p0 = group * 2304 + ti * 256;
        const int xhi = (p0 + 255) / 96;
        // stage rows for next tile-pair (disjoint ring slots; overlaps compute)
        if (ti < 8) {
            const int xhin = (p0 + 511) / 96;
            for (int gx = xhi + 2; gx <= xhin + 1; gx++) stage_row(sin_s, hb, gx, tid);
        }

        int slotoff[2][2][3];
#pragma unroll
        for (int mt = 0; mt < 2; mt++)
#pragma unroll
            for (int hf = 0; hf < 2; hf++) {
                int p = mg * 32 + mt * 16 + hf * 8 + g;
                int gp = p0 + p, px = gp / 96, py = gp - px * 96;
#pragma unroll
                for (int dx = 0; dx < 3; dx++)
                    slotoff[mt][hf][dx] = ((px + dx - 1 + 8) & 7) * ROWE + py * SINW;
            }

        float acc[2][4][4];
#pragma unroll
        for (int mt = 0; mt < 2; mt++)
#pragma unroll
            for (int nt = 0; nt < 4; nt++)
#pragma unroll
                for (int i = 0; i < 4; i++) acc[mt][nt][i] = 0.f;

#pragma unroll
        for (int tap = 0; tap < 9; tap++) {
            const int dx = tap / 3, dy = tap - dx * 3;
            const int cb = dy * SINW + tg * 2;
#pragma unroll
            for (int kk = 0; kk < 4; kk++) {
                const int ko = kk * 16;
                uint32_t A[2][4];
#pragma unroll
                for (int mt = 0; mt < 2; mt++) {
                    A[mt][0] = *(const uint32_t*)&sin_s[slotoff[mt][0][dx] + cb + ko];
                    A[mt][1] = *(const uint32_t*)&sin_s[slotoff[mt][1][dx] + cb + ko];
                    A[mt][2] = *(const uint32_t*)&sin_s[slotoff[mt][0][dx] + cb + ko + 8];
                    A[mt][3] = *(const uint32_t*)&sin_s[slotoff[mt][1][dx] + cb + ko + 8];
                }
                const int kbase = tap * 64 + ko;
#pragma unroll
                for (int nt = 0; nt < 4; nt++) {
                    const int co = nh * 32 + nt * 8 + g;
                    uint32_t b0 = *(const uint32_t*)&wk_s[co * WKS + kbase + tg * 2];
                    uint32_t b1 = *(const uint32_t*)&wk_s[co * WKS + kbase + 8 + tg * 2];
#pragma unroll
                    for (int mt = 0; mt < 2; mt++)
                        mma_bf16(acc[mt][nt], A[mt][0], A[mt][1], A[mt][2], A[mt][3], b0, b1);
                }
            }
        }

        // writeout + BN0 stats
        float* ob = obB + p0;
#pragma unroll
        for (int nt = 0; nt < 4; nt++) {
            const int co0 = nh * 32 + nt * 8 + tg * 2;
#pragma unroll
            for (int mt = 0; mt < 2; mt++) {
                const int pr = mg * 32 + mt * 16 + g;
                float v0 = acc[mt][nt][0] + bv[nt][0];
                float v1 = acc[mt][nt][1] + bv[nt][1];
                float v2 = acc[mt][nt][2] + bv[nt][0];
                float v3 = acc[mt][nt][3] + bv[nt][1];
                ob[(size_t)co0 * TS_ + pr]           = v0;
                ob[(size_t)(co0 + 1) * TS_ + pr]     = v1;
                ob[(size_t)co0 * TS_ + pr + 8]       = v2;
                ob[(size_t)(co0 + 1) * TS_ + pr + 8] = v3;
                st_s[nt * 2]     += v0 + v2;
                st_q[nt * 2]     += v0 * v0 + v2 * v2;
                st_s[nt * 2 + 1] += v1 + v3;
                st_q[nt * 2 + 1] += v1 * v1 + v3 * v3;
            }
        }
        __syncthreads();
    }

    // BN0 stats reduce: over g lanes (bits 2..4)
#pragma unroll
    for (int i = 0; i < 8; i++) {
        st_s[i] += __shfl_xor_sync(0xffffffffu, st_s[i], 4);
        st_s[i] += __shfl_xor_sync(0xffffffffu, st_s[i], 8);
        st_s[i] += __shfl_xor_sync(0xffffffffu, st_s[i], 16);
        st_q[i] += __shfl_xor_sync(0xffffffffu, st_q[i], 4);
        st_q[i] += __shfl_xor_sync(0xffffffffu, st_q[i], 8);
        st_q[i] += __shfl_xor_sync(0xffffffffu, st_q[i], 16);
    }
    if (lane < 4) {
#pragma unroll
        for (int nt = 0; nt < 4; nt++)
#pragma unroll
            for (int r = 0; r < 2; r++) {
                const int co = nh * 32 + nt * 8 + lane * 2 + r;
                atomicAdd(&s_st[co], st_s[nt * 2 + r]);
                atomicAdd(&s_st[64 + co], st_q[nt * 2 + r]);
            }
    }
    __syncthreads();
    if (tid < 128) atomicAdd(&g_sum0[tid], s_st[tid]);
}

// ---------------- zero accumulators ----------------
__global__ void k_zero() {
    int i = threadIdx.x;
    if (i < 128) { g_sum0[i] = 0.f; g_sum1[i] = 0.f; }
}

// ---------------- BN coefficients ----------------
__global__ void k_coef(int mode, const float* __restrict__ g,
                       const float* __restrict__ beta) {
    const int c = threadIdx.x;
    if (c >= 64) return;
    const float* sums = mode ? g_sum1 : g_sum0;
    float* coef = mode ? g_coef1 : g_coef0;
    const float inv = 1.0f / CNT_;
    float mu = sums[c] * inv;
    float var = sums[64 + c] * inv - mu * mu;
    float A = g[c] * rsqrtf(var + 1e-5f);
    coef[c] = A;
    coef[64 + c] = beta[c] - mu * A;
}

// ---------------- qkv: bf16 mma, M=192, K=64, N=128-pixel tiles ----------------
__global__ void __launch_bounds__(256) k_qkv_mma(const float* __restrict__ bias) {
    __shared__ __nv_bfloat16 Ws[192 * 72];
    __shared__ __nv_bfloat16 Xt[128 * 72];
    const int tid = threadIdx.x, lane = tid & 31, wid = tid >> 5;
    const int j0 = blockIdx.x * 128;
    const int bt = blockIdx.y, b = bt >> 3, t = bt & 7;

    {
        const uint4* src = (const uint4*)g_wqkv;
        for (int e = tid; e < 1536; e += 256) {
            int co = e >> 3, q = e & 7;
            *(uint4*)&Ws[co * 72 + q * 8] = src[e];
        }
    }
    {
        const float* xb = g_x + ((size_t)(b * C_) * T_ + t) * S_ + j0;
        for (int e = tid; e < 4096; e += 256) {
            int kp = e >> 7, n = e & 127;
            int k0 = kp * 2;
            float v0 = lk(fmaf(xb[(size_t)k0 * TS_ + n], g_coef0[k0], g_coef0[64 + k0]));
            float v1 = lk(fmaf(xb[(size_t)(k0 + 1) * TS_ + n], g_coef0[k0 + 1], g_coef0[64 + k0 + 1]));
            *(uint32_t*)&Xt[n * 72 + k0] = packbf(v0, v1);
        }
    }
    __syncthreads();

    const int mg = wid >> 1, nh = wid & 1;
    const int g = lane >> 2, tg = lane & 3;

    float acc[3][8][4];
#pragma unroll
    for (int mt = 0; mt < 3; mt++)
#pragma unroll
        for (int nt = 0; nt < 8; nt++)
#pragma unroll
            for (int i = 0; i < 4; i++) acc[mt][nt][i] = 0.f;

#pragma unroll
    for (int kk = 0; kk < 4; kk++) {
        const int ko = kk * 16 + tg * 2;
        uint32_t A[3][4];
#pragma unroll
        for (int mt = 0; mt < 3; mt++) {
            const int r = mg * 48 + mt * 16;
            A[mt][0] = *(const uint32_t*)&Ws[(r + g) * 72 + ko];
            A[mt][1] = *(const uint32_t*)&Ws[(r + g + 8) * 72 + ko];
            A[mt][2] = *(const uint32_t*)&Ws[(r + g) * 72 + ko + 8];
            A[mt][3] = *(const uint32_t*)&Ws[(r + g + 8) * 72 + ko + 8];
        }
#pragma unroll
        for (int nt = 0; nt < 8; nt++) {
            const int np = nh * 64 + nt * 8 + g;
            uint32_t b0 = *(const uint32_t*)&Xt[np * 72 + ko];
            uint32_t b1 = *(const uint32_t*)&Xt[np * 72 + ko + 8];
#pragma unroll
            for (int mt = 0; mt < 3; mt++)
                mma_bf16(acc[mt][nt], A[mt][0], A[mt][1], A[mt][2], A[mt][3], b0, b1);
        }
    }

    const int ncol = b * S_ + j0 + nh * 64;
#pragma unroll
    for (int mt = 0; mt < 3; mt++) {
        const int co0 = mg * 48 + mt * 16 + g;
#pragma unroll
        for (int r = 0; r < 2; r++) {
            const int co = co0 + r * 8;
            const int z = co >> 6, mo = co & 63;
            const float bb = __ldg(&bias[co]);
            __nv_bfloat16* op = g_qkvh + (size_t)z * QSZ_ + (size_t)(t * 64 + mo) * N_ + ncol;
#pragma unroll
            for (int nt = 0; nt < 8; nt++) {
                uint32_t pk = packbf(acc[mt][nt][r * 2] + bb, acc[mt][nt][r * 2 + 1] + bb);
                *(uint32_t*)&op[nt * 8 + tg * 2] = pk;
            }
        }
    }
}

// ---------------- attention core (bf16 io) ----------------
__global__ void __launch_bounds__(128) k_attn() {
    const int n = blockIdx.x * 128 + threadIdx.x;
    const int hh = blockIdx.y;
    const int cb = hh * 8;
    const __nv_bfloat16* qp = g_qkvh;
    const __nv_bfloat16* kp = g_qkvh + QSZ_;
    const __nv_bfloat16* vp = g_qkvh + 2 * (size_t)QSZ_;

    float kk[8][8], vv[8][8];
#pragma unroll
    for (int tt = 0; tt < 8; tt++)
#pragma unroll
        for (int d = 0; d < 8; d++) {
            const size_t idx = (size_t)(tt * 64 + cb + d) * N_ + n;
            kk[tt][d] = __bfloat162float(kp[idx]);
            vv[tt][d] = __bfloat162float(vp[idx]);
        }
    const float scale = 0.3535533905932738f;
#pragma unroll
    for (int tq = 0; tq < 8; tq++) {
        float q[8];
#pragma unroll
        for (int d = 0; d < 8; d++)
            q[d] = __bfloat162float(qp[(size_t)(tq * 64 + cb + d) * N_ + n]) * scale;
        float s[8];
        float mx = -1e30f;
#pragma unroll
        for (int tt = 0; tt < 8; tt++) {
            float a = 0.f;
#pragma unroll
            for (int d = 0; d < 8; d++) a = fmaf(q[d], kk[tt][d], a);
            s[tt] = a;
            mx = fmaxf(mx, a);
        }
        float sum = 0.f;
#pragma unroll
        for (int tt = 0; tt < 8; tt++) { s[tt] = __expf(s[tt] - mx); sum += s[tt]; }
        const float inv = 1.0f / sum;
#pragma unroll
        for (int d = 0; d < 8; d++) {
            float o = 0.f;
#pragma unroll
            for (int tt = 0; tt < 8; tt++) o = fmaf(s[tt], vv[tt][d], o);
            g_oh[(size_t)(tq * 64 + cb + d) * N_ + n] = __float2bfloat16(o * inv);
        }
    }
}

// ---------------- out_proj: bf16 mma + fused residual + BN1 stats ----------------
__global__ void __launch_bounds__(256) k_outproj_mma(const float* __restrict__ bias) {
    __shared__ __nv_bfloat16 Ws[64 * 72];
    __shared__ __nv_bfloat16 Ot[128 * 72];
    __shared__ float s_st[128];
    const int tid = threadIdx.x, lane = tid & 31, wid = tid >> 5;
    const int j0 = blockIdx.x * 128;
    const int bt = blockIdx.y, b = bt >> 3, t = bt & 7;

    if (tid < 128) s_st[tid] = 0.f;
    {
        const uint4* src = (const uint4*)g_wout;
        for (int e = tid; e < 512; e += 256) {
            int co = e >> 3, q = e & 7;
            *(uint4*)&Ws[co * 72 + q * 8] = src[e];
        }
    }
    {
        const __nv_bfloat16* ob = g_oh + (size_t)(t * 64) * N_ + b * S_ + j0;
        for (int e = tid; e < 4096; e += 256) {
            int kp = e >> 7, n = e & 127;
            int k0 = kp * 2;
            __nv_bfloat162 p;
            p.x = ob[(size_t)k0 * N_ + n];
            p.y = ob[(size_t)(k0 + 1) * N_ + n];
            *(uint32_t*)&Ot[n * 72 + k0] = *(uint32_t*)&p;
        }
    }
    __syncthreads();

    const int mg = wid >> 2, ng = wid & 3;
    const int g = lane >> 2, tg = lane & 3;

    float acc[2][4][4];
#pragma unroll
    for (int mt = 0; mt < 2; mt++)
#pragma unroll
        for (int nt = 0; nt < 4; nt++)
#pragma unroll
            for (int i = 0; i < 4; i++) acc[mt][nt][i] = 0.f;

#pragma unroll
    for (int kk = 0; kk < 4; kk++) {
        const int ko = kk * 16 + tg * 2;
        uint32_t A[2][4];
#pragma unroll
        for (int mt = 0; mt < 2; mt++) {
            const int r = mg * 32 + mt * 16;
            A[mt][0] = *(const uint32_t*)&Ws[(r + g) * 72 + ko];
            A[mt][1] = *(const uint32_t*)&Ws[(r + g + 8) * 72 + ko];
            A[mt][2] = *(const uint32_t*)&Ws[(r + g) * 72 + ko + 8];
            A[mt][3] = *(const uint32_t*)&Ws[(r + g + 8) * 72 + ko + 8];
        }
#pragma unroll
        for (int nt = 0; nt < 4; nt++) {
            const int np = ng * 32 + nt * 8 + g;
            uint32_t b0 = *(const uint32_t*)&Ot[np * 72 + ko];
            uint32_t b1 = *(const uint32_t*)&Ot[np * 72 + ko + 8];
#pragma unroll
            for (int mt = 0; mt < 2; mt++)
                mma_bf16(acc[mt][nt], A[mt][0], A[mt][1], A[mt][2], A[mt][3], b0, b1);
        }
    }

    float ps[2][2], pq[2][2];
#pragma unroll
    for (int mt = 0; mt < 2; mt++)
#pragma unroll
        for (int r = 0; r < 2; r++) { ps[mt][r] = 0.f; pq[mt][r] = 0.f; }

#pragma unroll
    for (int mt = 0; mt < 2; mt++) {
#pragma unroll
        for (int r = 0; r < 2; r++) {
            const int co = mg * 32 + mt * 16 + r * 8 + g;
            const float bb = __ldg(&bias[co]);
            const float A0 = g_coef0[co], B0 = g_coef0[64 + co];
            const size_t rowb = ((size_t)(b * C_ + co) * T_ + t) * S_ + j0;
#pragma unroll
            for (int nt = 0; nt < 4; nt++) {
                const int px = ng * 32 + nt * 8 + tg * 2;
                float2 xv = *(const float2*)&g_x[rowb + px];
                float zx = lk(fmaf(xv.x, A0, B0)) + acc[mt][nt][r * 2] + bb;
                float zy = lk(fmaf(xv.y, A0, B0)) + acc[mt][nt][r * 2 + 1] + bb;
                *(uint32_t*)&g_zh[rowb + px] = packbf(zx, zy);
                ps[mt][r] += zx + zy;
                pq[mt][r] += zx * zx + zy * zy;
            }
        }
    }

#pragma unroll
    for (int mt = 0; mt < 2; mt++)
#pragma unroll
        for (int r = 0; r < 2; r++) {
            ps[mt][r] += __shfl_xor_sync(0xffffffffu, ps[mt][r], 1);
            ps[mt][r] += __shfl_xor_sync(0xffffffffu, ps[mt][r], 2);
            pq[mt][r] += __shfl_xor_sync(0xffffffffu, pq[mt][r], 1);
            pq[mt][r] += __shfl_xor_sync(0xffffffffu, pq[mt][r], 2);
        }
    if ((lane & 3) == 0) {
#pragma unroll
        for (int mt = 0; mt < 2; mt++)
#pragma unroll
            for (int r = 0; r < 2; r++) {
                const int co = mg * 32 + mt * 16 + r * 8 + g;
                atomicAdd(&s_st[co], ps[mt][r]);
                atomicAdd(&s_st[64 + co], pq[mt][r]);
            }
    }
    __syncthreads();
    if (tid < 128) atomicAdd(&g_sum1[tid], s_st[tid]);
}

// ---------------- spatial mean of leaky(bn1(z)), bf16 input ----------------
__global__ void __launch_bounds__(256) k_mean() {
    const int bid = blockIdx.x;
    const int c = (bid >> 3) & 63;
    const float A = g_coef1[c], Bv = g_coef1[64 + c];
    const uint32_t* p = (const uint32_t*)(g_zh + (size_t)bid * S_);
    float s = 0.f;
    for (int i = threadIdx.x; i < S_ / 2; i += 256) {
        uint32_t u = p[i];
        __nv_bfloat162 bp = *(__nv_bfloat162*)&u;
        s += lk(fmaf(__bfloat162float(bp.x), A, Bv));
        s += lk(fmaf(__bfloat162float(bp.y), A, Bv));
    }
#pragma unroll
    for (int off = 16; off; off >>= 1) s += __shfl_down_sync(0xffffffffu, s, off);
    __shared__ float wa[8];
    const int lane = threadIdx.x & 31, wid = threadIdx.x >> 5;
    if (lane == 0) wa[wid] = s;
    __syncthreads();
    if (threadIdx.x == 0) {
        float ts = 0.f;
#pragma unroll
        for (int i = 0; i < 8; i++) ts += wa[i];
        g_m[bid] = ts * (1.0f / (float)S_);
    }
}

// ---------------- per-(b,t) 5x5 kernels ----------------
__global__ void k_kern(const float* __restrict__ w1, const float* __restrict__ b1) {
    const int idx = blockIdx.x * 256 + threadIdx.x;
    if (idx >= B_ * T_ * 25) return;
    const int b = idx / (T_ * 25);
    const int r = idx - b * (T_ * 25);
    const int t = r / 25;
    const int o = r - t * 25;
    float a = b1[o];
#pragma unroll 8
    for (int c = 0; c < 64; c++)
        a = fmaf(g_m[(b * C_ + c) * T_ + t], w1[o * 64 + c], a);
    g_kern[(b * T_ + t) * 25 + o] = a;
}

// ---------------- dynamic depthwise 5x5 conv ----------------
__global__ void __launch_bounds__(256) k_dynconv(const float* __restrict__ h,
                                                 float* __restrict__ out) {
    __shared__ float sp[100 * 100];
    __shared__ float sk[25];
    const int bid = blockIdx.x;
    const int b = bid >> 9;
    const int t = bid & 7;
    const int tid = threadIdx.x;
    const float* base = h + (size_t)bid * S_;

    for (int i = tid; i < 10000; i += 256) sp[i] = 0.f;
    if (tid < 25) sk[tid] = g_kern[(b * T_ + t) * 25 + tid];
    __syncthreads();
    for (int i = tid; i < S_; i += 256) {
        const int r = i / 96, col = i - r * 96;
        sp[(r + 2) * 100 + col + 2] = base[i];
    }
    __syncthreads();

    float kr[25];
#pragma unroll
    for (int q = 0; q < 25; q++) kr[q] = sk[q];

    float* ob = out + (size_t)bid * S_;
    for (int i = tid; i < S_; i += 256) {
        const int r = i / 96, col = i - r * 96;
        const float* pp = &sp[r * 100 + col];
        float a = 0.f;
#pragma unroll
        for (int ii = 0; ii < 5; ii++)
#pragma unroll
            for (int jj = 0; jj < 5; jj++)
                a = fmaf(pp[ii * 100 + jj], kr[ii * 5 + jj], a);
        ob[i] = a;
    }
}

// ---------------- launch ----------------
extern "C" void kernel_launch(void* const* d_in, const int* in_sizes, int n_in,
                              void* d_out, int out_size) {
    const float* h       = (const float*)d_in[0];
    const float* conv0_w = (const float*)d_in[1];
    const float* conv0_b = (const float*)d_in[2];
    const float* bn0_g   = (const float*)d_in[3];
    const float* bn0_b   = (const float*)d_in[4];
    const float* bn1_g   = (const float*)d_in[5];
    const float* bn1_b   = (const float*)d_in[6];
    const float* inW     = (const float*)d_in[7];
    const float* inB     = (const float*)d_in[8];
    const float* outW    = (const float*)d_in[9];
    const float* outB    = (const float*)d_in[10];
    const float* c1w     = (const float*)d_in[11];
    const float* c1b     = (const float*)d_in[12];
    float* out = (float*)d_out;

    cudaFuncSetAttribute(k_conv0_mma, cudaFuncAttributeMaxDynamicSharedMemorySize,
                         SM_CONV_TOT);

    k_zero<<<1, 128>>>();
    k_wprep<<<(64 * 576 + 255) / 256, 256>>>(conv0_w);
    k_wprep2<<<(192 * 64 + 255) / 256, 256>>>(inW, outW);
    k_conv0_mma<<<dim3(4, B_ * T_), 512, SM_CONV_TOT>>>(h, conv0_b);
    k_coef<<<1, 64>>>(0, bn0_g, bn0_b);
    k_qkv_mma<<<dim3(S_ / 128, B_ * T_), 256>>>(inB);
    k_attn<<<dim3(N_ / 128, 8), 128>>>();
    k_outproj_mma<<<dim3(S_ / 128, B_ * T_), 256>>>(outB);
    k_coef<<<1, 64>>>(1, bn1_g, bn1_b);
    k_mean<<<B_ * C_ * T_, 256>>>();
    k_kern<<<4, 256>>>(c1w, c1b);
    k_dynconv<<<B_ * C_ * T_, 256>>>(h, out);
}

// round 10
// speedup vs baseline: 1.0200x; 1.0200x over previous
#include <cuda_runtime.h>
#include <cuda_bf16.h>
#include <cstdint>

// Problem constants
#define B_ 4
#define C_ 64
#define T_ 8
#define X_ 96
#define Y_ 96
#define S_ 9216            // X_*Y_
#define N_ 36864           // B_*S_
#define TS_ 73728          // T_*S_
#define TOTAL_ 18874368    // B_*C_*T_*S_
#define QSZ_ 18874368      // T_*C_*N_
#define CNT_ 294912.0f     // B_*T_*S_

// -------- scratch (device globals; no runtime allocation) --------
__device__ __nv_bfloat16 g_xh[TOTAL_];            // conv0 raw output (pre-BN0), bf16
__device__ __nv_bfloat16 g_qkvh[3 * QSZ_];        // q,k,v bf16, [z][t][c][n]
__device__ __nv_bfloat16 g_zh[TOTAL_];            // residual + out_proj (pre-BN1), bf16
__device__ float g_sum0[128];
__device__ float g_sum1[128];
__device__ float g_coef0[128];                    // bn0: A[0:64], B[64:128]
__device__ float g_coef1[128];
__device__ float g_m[B_ * C_ * T_];
__device__ float g_kern[B_ * T_ * 25];
__device__ __align__(16) __nv_bfloat16 g_wk[64 * 576];   // conv0 [co][k], k=tap*64+ci
__device__ __align__(16) __nv_bfloat16 g_wqkv[192 * 64]; // in_proj bf16
__device__ __align__(16) __nv_bfloat16 g_wout[64 * 64];  // out_proj bf16

__device__ __forceinline__ float lk(float v) { return v >= 0.f ? v : 0.01f * v; }

__device__ __forceinline__ void mma_bf16(float* c, uint32_t a0, uint32_t a1,
                                         uint32_t a2, uint32_t a3,
                                         uint32_t b0, uint32_t b1) {
    asm volatile(
        "mma.sync.aligned.m16n8k16.row.col.f32.bf16.bf16.f32 "
        "{%0,%1,%2,%3}, {%4,%5,%6,%7}, {%8,%9}, {%0,%1,%2,%3};"
        : "+f"(c[0]), "+f"(c[1]), "+f"(c[2]), "+f"(c[3])
        : "r"(a0), "r"(a1), "r"(a2), "r"(a3), "r"(b0), "r"(b1));
}

__device__ __forceinline__ uint32_t packbf(float a, float b) {
    __nv_bfloat162 p = __floats2bfloat162_rn(a, b);
    return *(uint32_t*)&p;
}

__device__ __forceinline__ uint32_t smem_u32(const void* p) {
    uint32_t a;
    asm("{ .reg .u64 t; cvta.to.shared.u64 t, %1; cvt.u32.u64 %0, t; }" : "=r"(a) : "l"(p));
    return a;
}

__device__ __forceinline__ void ldsm_x4(uint32_t* r, uint32_t addr) {
    asm volatile("ldmatrix.sync.aligned.m8n8.x4.shared.b16 {%0,%1,%2,%3}, [%4];"
        : "=r"(r[0]), "=r"(r[1]), "=r"(r[2]), "=r"(r[3]) : "r"(addr));
}
__device__ __forceinline__ void ldsm_x4_t(uint32_t* r, uint32_t addr) {
    asm volatile("ldmatrix.sync.aligned.m8n8.x4.trans.shared.b16 {%0,%1,%2,%3}, [%4];"
        : "=r"(r[0]), "=r"(r[1]), "=r"(r[2]), "=r"(r[3]) : "r"(addr));
}

// ===================== combined prep (zero + all weight converts) =====================
__global__ void k_prep(const float* __restrict__ w, const float* __restrict__ inW,
                       const float* __restrict__ outW) {
    int i = blockIdx.x * 256 + threadIdx.x;
    if (i < 128) { g_sum0[i] = 0.f; g_sum1[i] = 0.f; }
    if (i < 64 * 576) {
        int co = i / 576, k = i - co * 576;
        g_wk[i] = __float2bfloat16(w[(co * 64 + (k & 63)) * 9 + (k >> 6)]);
    }
    if (i < 192 * 64) g_wqkv[i] = __float2bfloat16(inW[i]);
    if (i < 64 * 64) g_wout[i] = __float2bfloat16(outW[i]);
}

// ===================== conv0: persistent bf16 mma + ldmatrix, 512 thr =====================
#define SINW 72
#define ROWE (98 * SINW)                // 7056 elems per row slot
#define RING 8
#define WKS 584
#define SM_WK_OFF (RING * ROWE * 2)     // 112896 bytes
#define SM_CONV_TOT (SM_WK_OFF + 64 * WKS * 2)   // 187648 bytes

__device__ __forceinline__ void stage_row(__nv_bfloat16* sin_s, const float* hb,
                                          int gx, int tid) {
    const int slot = (gx + 8) & 7;
    __nv_bfloat16* dst = sin_s + slot * ROWE;
    if ((unsigned)gx >= 96u) {
        for (int e = tid; e < 6144; e += 512) {
            int ci = e / 96, y = e - ci * 96;
            dst[(y + 1) * SINW + ci] = __float2bfloat16(0.f);
        }
    } else {
        const float* hp = hb + (size_t)gx * 96;
        for (int e = tid; e < 6144; e += 512) {
            int ci = e / 96, y = e - ci * 96;
            dst[(y + 1) * SINW + ci] = __float2bfloat16(hp[(size_t)ci * TS_ + y]);
        }
    }
    if (tid < 64) dst[tid] = __float2bfloat16(0.f);
    else if (tid < 128) dst[97 * SINW + (tid - 64)] = __float2bfloat16(0.f);
}

__global__ void __launch_bounds__(512)
k_conv0_mma(const float* __restrict__ h, const float* __restrict__ bias) {
    extern __shared__ char smem[];
    __nv_bfloat16* sin_s = (__nv_bfloat16*)smem;
    __nv_bfloat16* wk_s = (__nv_bfloat16*)(smem + SM_WK_OFF);
    __shared__ float s_st[128];

    const int tid = threadIdx.x, lane = tid & 31, wid = tid >> 5;
    const int group = blockIdx.x, bt = blockIdx.y, b = bt >> 3, t = bt & 7;
    const float* hb = h + (size_t)b * (64 * TS_) + (size_t)t * S_;

    if (tid < 128) s_st[tid] = 0.f;
    {
        const uint4* src = (const uint4*)g_wk;
        for (int e = tid; e < 4608; e += 512) {
            int co = e / 72, q = e - co * 72;
            *(uint4*)&wk_s[co * WKS + q * 8] = src[e];
        }
    }
    {
        const int p0 = group * 2304;
        const int xlo = p0 / 96, xhi = (p0 + 255) / 96;
        for (int gx = xlo - 1; gx <= xhi + 1; gx++) stage_row(sin_s, hb, gx, tid);
    }
    __syncthreads();

    const int mg = wid >> 1, nh = wid & 1;
    const int g = lane >> 2, tg = lane & 3;

    const uint32_t sin_b = smem_u32(sin_s);
    const uint32_t wk_b = smem_u32(wk_s);

    // B (weights) per-lane ldmatrix addresses for the two nt-pairs
    uint32_t wkaddr[2];
    {
        const int koff = ((lane >> 3) & 1) * 8;
        const int cosub = (lane & 7) + ((lane >> 4) & 1) * 8;
#pragma unroll
        for (int ntp = 0; ntp < 2; ntp++) {
            const int co = nh * 32 + ntp * 16 + cosub;
            wkaddr[ntp] = wk_b + (uint32_t)(co * WKS + koff) * 2;
        }
    }
    const uint32_t khiA = (uint32_t)((lane >> 4) * 16);  // +8 k elems for matrices 2,3

    float bv[4][2];
#pragma unroll
    for (int nt = 0; nt < 4; nt++) {
        const int co0 = nh * 32 + nt * 8 + tg * 2;
        bv[nt][0] = __ldg(&bias[co0]);
        bv[nt][1] = __ldg(&bias[co0 + 1]);
    }

    float st_s[8], st_q[8];
#pragma unroll
    for (int i = 0; i < 8; i++) { st_s[i] = 0.f; st_q[i] = 0.f; }

    __nv_bfloat16* obB = g_xh + (size_t)b * (64 * TS_) + (size_t)t * S_;

    for (int ti = 0; ti < 9; ti++) {
        const int p0 = group * 2304 + ti * 256;
        const int xhi = (p0 + 255) / 96;
        if (ti < 8) {
            const int xhin = (p0 + 511) / 96;
            for (int gx = xhi + 2; gx <= xhin + 1; gx++) stage_row(sin_s, hb, gx, tid);
        }

        // per-lane A row bases (handles row crossings per lane)
        uint32_t aRB[2][3];
        {
            const int plbase = p0 + mg * 32 + (lane & 15);
#pragma unroll
            for (int mt = 0; mt < 2; mt++) {
                const int pl = plbase + mt * 16;
                const int px = pl / 96, py = pl - px * 96;
#pragma unroll
                for (int dx = 0; dx < 3; dx++)
                    aRB[mt][dx] = sin_b +
                        (uint32_t)(((px + dx + 7) & 7) * ROWE + py * SINW) * 2 + khiA;
            }
        }

        float acc[2][4][4];
#pragma unroll
        for (int mt = 0; mt < 2; mt++)
#pragma unroll
            for (int nt = 0; nt < 4; nt++)
#pragma unroll
                for (int i = 0; i < 4; i++) acc[mt][nt][i] = 0.f;

#pragma unroll
        for (int tap = 0; tap < 9; tap++) {
            const int dx = tap / 3, dy = tap - dx * 3;
            const uint32_t dyoff = (uint32_t)(dy * SINW) * 2;
#pragma unroll
            for (int kk = 0; kk < 4; kk++) {
                const uint32_t ko2 = (uint32_t)kk * 32;
                uint32_t A0[4], A1[4], Bf0[4], Bf1[4];
                ldsm_x4(A0, aRB[0][dx] + dyoff + ko2);
                ldsm_x4(A1, aRB[1][dx] + dyoff + ko2);
                const uint32_t bk = (uint32_t)(tap * 64 + kk * 16) * 2;
                ldsm_x4(Bf0, wkaddr[0] + bk);
                ldsm_x4(Bf1, wkaddr[1] + bk);
                mma_bf16(acc[0][0], A0[0], A0[1], A0[2], A0[3], Bf0[0], Bf0[1]);
                mma_bf16(acc[1][0], A1[0], A1[1], A1[2], A1[3], Bf0[0], Bf0[1]);
                mma_bf16(acc[0][1], A0[0], A0[1], A0[2], A0[3], Bf0[2], Bf0[3]);
                mma_bf16(acc[1][1], A1[0], A1[1], A1[2], A1[3], Bf0[2], Bf0[3]);
                mma_bf16(acc[0][2], A0[0], A0[1], A0[2], A0[3], Bf1[0], Bf1[1]);
                mma_bf16(acc[1][2], A1[0], A1[1], A1[2], A1[3], Bf1[0], Bf1[1]);
                mma_bf16(acc[0][3], A0[0], A0[1], A0[2], A0[3], Bf1[2], Bf1[3]);
                mma_bf16(acc[1][3], A1[0], A1[1], A1[2], A1[3], Bf1[2], Bf1[3]);
            }
        }

        // writeout bf16 + BN0 stats (fp32, pre-rounding)
        __nv_bfloat16* ob = obB + p0;
#pragma unroll
        for (int nt = 0; nt < 4; nt++) {
            const int co0 = nh * 32 + nt * 8 + tg * 2;
#pragma unroll
            for (int mt = 0; mt < 2; mt++) {
                const int pr = mg * 32 + mt * 16 + g;
                float v0 = acc[mt][nt][0] + bv[nt][0];
                float v1 = acc[mt][nt][1] + bv[nt][1];
                float v2 = acc[mt][nt][2] + bv[nt][0];
                float v3 = acc[mt][nt][3] + bv[nt][1];
                ob[(size_t)co0 * TS_ + pr]           = __float2bfloat16(v0);
                ob[(size_t)(co0 + 1) * TS_ + pr]     = __float2bfloat16(v1);
                ob[(size_t)co0 * TS_ + pr + 8]       = __float2bfloat16(v2);
                ob[(size_t)(co0 + 1) * TS_ + pr + 8] = __float2bfloat16(v3);
                st_s[nt * 2]     += v0 + v2;
                st_q[nt * 2]     += v0 * v0 + v2 * v2;
                st_s[nt * 2 + 1] += v1 + v3;
                st_q[nt * 2 + 1] += v1 * v1 + v3 * v3;
            }
        }
        __syncthreads();
    }

#pragma unroll
    for (int i = 0; i < 8; i++) {
        st_s[i] += __shfl_xor_sync(0xffffffffu, st_s[i], 4);
        st_s[i] += __shfl_xor_sync(0xffffffffu, st_s[i], 8);
        st_s[i] += __shfl_xor_sync(0xffffffffu, st_s[i], 16);
        st_q[i] += __shfl_xor_sync(0xffffffffu, st_q[i], 4);
        st_q[i] += __shfl_xor_sync(0xffffffffu, st_q[i], 8);
        st_q[i] += __shfl_xor_sync(0xffffffffu, st_q[i], 16);
    }
    if (lane < 4) {
#pragma unroll
        for (int nt = 0; nt < 4; nt++)
#pragma unroll
            for (int r = 0; r < 2; r++) {
                const int co = nh * 32 + nt * 8 + lane * 2 + r;
                atomicAdd(&s_st[co], st_s[nt * 2 + r]);
                atomicAdd(&s_st[64 + co], st_q[nt * 2 + r]);
            }
    }
    __syncthreads();
    if (tid < 128) atomicAdd(&g_sum0[tid], s_st[tid]);
}

// ---------------- BN coefficients ----------------
__global__ void k_coef(int mode, const float* __restrict__ g,
                       const float* __restrict__ beta) {
    const int c = threadIdx.x;
    if (c >= 64) return;
    const float* sums = mode ? g_sum1 : g_sum0;
    float* coef = mode ? g_coef1 : g_coef0;
    const float inv = 1.0f / CNT_;
    float mu = sums[c] * inv;
    float var = sums[64 + c] * inv - mu * mu;
    float A = g[c] * rsqrtf(var + 1e-5f);
    coef[c] = A;
    coef[64 + c] = beta[c] - mu * A;
}

// ---------------- qkv: bf16 mma, M=192, K=64, N=128-pixel tiles ----------------
__global__ void __launch_bounds__(256) k_qkv_mma(const float* __restrict__ bias) {
    __shared__ __nv_bfloat16 Ws[192 * 72];
    __shared__ __nv_bfloat16 Xt[128 * 72];
    const int tid = threadIdx.x, lane = tid & 31, wid = tid >> 5;
    const int j0 = blockIdx.x * 128;
    const int bt = blockIdx.y, b = bt >> 3, t = bt & 7;

    {
        const uint4* src = (const uint4*)g_wqkv;
        for (int e = tid; e < 1536; e += 256) {
            int co = e >> 3, q = e & 7;
            *(uint4*)&Ws[co * 72 + q * 8] = src[e];
        }
    }
    {
        const __nv_bfloat16* xb = g_xh + ((size_t)(b * C_) * T_ + t) * S_ + j0;
        for (int e = tid; e < 4096; e += 256) {
            int kp = e >> 7, n = e & 127;
            int k0 = kp * 2;
            float x0 = __bfloat162float(xb[(size_t)k0 * TS_ + n]);
            float x1 = __bfloat162float(xb[(size_t)(k0 + 1) * TS_ + n]);
            float v0 = lk(fmaf(x0, g_coef0[k0], g_coef0[64 + k0]));
            float v1 = lk(fmaf(x1, g_coef0[k0 + 1], g_coef0[64 + k0 + 1]));
            *(uint32_t*)&Xt[n * 72 + k0] = packbf(v0, v1);
        }
    }
    __syncthreads();

    const int mg = wid >> 1, nh = wid & 1;
    const int g = lane >> 2, tg = lane & 3;

    float acc[3][8][4];
#pragma unroll
    for (int mt = 0; mt < 3; mt++)
#pragma unroll
        for (int nt = 0; nt < 8; nt++)
#pragma unroll
            for (int i = 0; i < 4; i++) acc[mt][nt][i] = 0.f;

#pragma unroll
    for (int kk = 0; kk < 4; kk++) {
        const int ko = kk * 16 + tg * 2;
        uint32_t A[3][4];
#pragma unroll
        for (int mt = 0; mt < 3; mt++) {
            const int r = mg * 48 + mt * 16;
            A[mt][0] = *(const uint32_t*)&Ws[(r + g) * 72 + ko];
            A[mt][1] = *(const uint32_t*)&Ws[(r + g + 8) * 72 + ko];
            A[mt][2] = *(const uint32_t*)&Ws[(r + g) * 72 + ko + 8];
            A[mt][3] = *(const uint32_t*)&Ws[(r + g + 8) * 72 + ko + 8];
        }
#pragma unroll
        for (int nt = 0; nt < 8; nt++) {
            const int np = nh * 64 + nt * 8 + g;
            uint32_t b0 = *(const uint32_t*)&Xt[np * 72 + ko];
            uint32_t b1 = *(const uint32_t*)&Xt[np * 72 + ko + 8];
#pragma unroll
            for (int mt = 0; mt < 3; mt++)
                mma_bf16(acc[mt][nt], A[mt][0], A[mt][1], A[mt][2], A[mt][3], b0, b1);
        }
    }

    const int ncol = b * S_ + j0 + nh * 64;
#pragma unroll
    for (int mt = 0; mt < 3; mt++) {
        const int co0 = mg * 48 + mt * 16 + g;
#pragma unroll
        for (int r = 0; r < 2; r++) {
            const int co = co0 + r * 8;
            const int z = co >> 6, mo = co & 63;
            const float bb = __ldg(&bias[co]);
            __nv_bfloat16* op = g_qkvh + (size_t)z * QSZ_ + (size_t)(t * 64 + mo) * N_ + ncol;
#pragma unroll
            for (int nt = 0; nt < 8; nt++) {
                uint32_t pk = packbf(acc[mt][nt][r * 2] + bb, acc[mt][nt][r * 2 + 1] + bb);
                *(uint32_t*)&op[nt * 8 + tg * 2] = pk;
            }
        }
    }
}

// ---------------- fused attention + out_proj + residual + BN1 stats ----------------
#define OTP 136
#define SM_WS_OFF (8 * 64 * OTP * 2)                 // 139264
#define SM_ATTN_TOT (SM_WS_OFF + 64 * 72 * 2)        // 148480

__global__ void __launch_bounds__(256)
k_attn_fused(const float* __restrict__ bias) {
    extern __shared__ char smem[];
    __nv_bfloat16* Ot = (__nv_bfloat16*)smem;             // [t][c][OTP]
    __nv_bfloat16* Ws = (__nv_bfloat16*)(smem + SM_WS_OFF);
    __shared__ float s_st[128];
    const int tid = threadIdx.x, lane = tid & 31, wid = tid >> 5;
    const int j0 = blockIdx.x * 128;
    const int b = j0 / S_;
    const int jb = j0 - b * S_;

    if (tid < 128) s_st[tid] = 0.f;
    {
        const uint4* src = (const uint4*)g_wout;
        for (int e = tid; e < 512; e += 256) {
            int co = e >> 3, q = e & 7;
            *(uint4*)&Ws[co * 72 + q * 8] = src[e];
        }
    }

    // ---- phase 1: attention for 128 n x 8 heads (4 heads per thread) ----
    {
        const int nl = tid & 127;
        const int hp = tid >> 7;
        const int n = j0 + nl;
        const __nv_bfloat16* qp = g_qkvh;
        const __nv_bfloat16* kp = g_qkvh + QSZ_;
        const __nv_bfloat16* vp = g_qkvh + 2 * (size_t)QSZ_;
        const float scale = 0.3535533905932738f;
        for (int i = 0; i < 4; i++) {
            const int cb = (hp * 4 + i) * 8;
            float kk[8][8], vv[8][8];
#pragma unroll
            for (int tt = 0; tt < 8; tt++)
#pragma unroll
                for (int d = 0; d < 8; d++) {
                    const size_t idx = (size_t)(tt * 64 + cb + d) * N_ + n;
                    kk[tt][d] = __bfloat162float(kp[idx]);
                    vv[tt][d] = __bfloat162float(vp[idx]);
                }
#pragma unroll
            for (int tq = 0; tq < 8; tq++) {
                float q[8];
#pragma unroll
                for (int d = 0; d < 8; d++)
                    q[d] = __bfloat162float(qp[(size_t)(tq * 64 + cb + d) * N_ + n]) * scale;
                float s[8];
                float mx = -1e30f;
#pragma unroll
                for (int tt = 0; tt < 8; tt++) {
                    float a = 0.f;
#pragma unroll
                    for (int d = 0; d < 8; d++) a = fmaf(q[d], kk[tt][d], a);
                    s[tt] = a;
                    mx = fmaxf(mx, a);
                }
                float sum = 0.f;
#pragma unroll
                for (int tt = 0; tt < 8; tt++) { s[tt] = __expf(s[tt] - mx); sum += s[tt]; }
                const float inv = 1.0f / sum;
#pragma unroll
                for (int d = 0; d < 8; d++) {
                    float o = 0.f;
#pragma unroll
                    for (int tt = 0; tt < 8; tt++) o = fmaf(s[tt], vv[tt][d], o);
                    Ot[(tq * 64 + cb + d) * OTP + nl] = __float2bfloat16(o * inv);
                }
            }
        }
    }
    __syncthreads();

    // ---- phase 2: out_proj per t + residual + z write + BN1 stats ----
    const int mg = wid >> 2, ng = wid & 3;
    const int g = lane >> 2, tg = lane & 3;
    const uint32_t ws_b = smem_u32(Ws);
    const uint32_t ot_b = smem_u32(Ot);
    const uint32_t aAddr0 = ws_b + (uint32_t)((mg * 32 + (lane & 15)) * 72 + (lane >> 4) * 8) * 2;
    const int krow_l = (lane & 7) + ((lane >> 3) & 1) * 8;
    const int np_l = ng * 32 + ((lane >> 4) & 1) * 8;

    float ps[2][2], pq[2][2];
#pragma unroll
    for (int mt = 0; mt < 2; mt++)
#pragma unroll
        for (int r = 0; r < 2; r++) { ps[mt][r] = 0.f; pq[mt][r] = 0.f; }

    for (int t = 0; t < 8; t++) {
        float acc[2][4][4];
#pragma unroll
        for (int mt = 0; mt < 2; mt++)
#pragma unroll
            for (int nt = 0; nt < 4; nt++)
#pragma unroll
                for (int i = 0; i < 4; i++) acc[mt][nt][i] = 0.f;

#pragma unroll
        for (int kk = 0; kk < 4; kk++) {
            uint32_t Af0[4], Af1[4], Bf0[4], Bf1[4];
            ldsm_x4(Af0, aAddr0 + (uint32_t)kk * 32);
            ldsm_x4(Af1, aAddr0 + 16 * 72 * 2 + (uint32_t)kk * 32);
            const uint32_t base =
                ot_b + (uint32_t)((t * 64 + kk * 16 + krow_l) * OTP + np_l) * 2;
            ldsm_x4_t(Bf0, base);
            ldsm_x4_t(Bf1, base + 32);   // +16 n elems
            mma_bf16(acc[0][0], Af0[0], Af0[1], Af0[2], Af0[3], Bf0[0], Bf0[1]);
            mma_bf16(acc[1][0], Af1[0], Af1[1], Af1[2], Af1[3], Bf0[0], Bf0[1]);
            mma_bf16(acc[0][1], Af0[0], Af0[1], Af0[2], Af0[3], Bf0[2], Bf0[3]);
            mma_bf16(acc[1][1], Af1[0], Af1[1], Af1[2], Af1[3], Bf0[2], Bf0[3]);
            mma_bf16(acc[0][2], Af0[0], Af0[1], Af0[2], Af0[3], Bf1[0], Bf1[1]);
            mma_bf16(acc[1][2], Af1[0], Af1[1], Af1[2], Af1[3], Bf1[0], Bf1[1]);
            mma_bf16(acc[0][3], Af0[0], Af0[1], Af0[2], Af0[3], Bf1[2], Bf1[3]);
            mma_bf16(acc[1][3], Af1[0], Af1[1], Af1[2], Af1[3], Bf1[2], Bf1[3]);
        }

#pragma unroll
        for (int mt = 0; mt < 2; mt++) {
#pragma unroll
            for (int r = 0; r < 2; r++) {
                const int co = mg * 32 + mt * 16 + r * 8 + g;
                const float bb = __ldg(&bias[co]);
                const float A0 = g_coef0[co], B0 = g_coef0[64 + co];
                const size_t rowb = ((size_t)(b * C_ + co) * T_ + t) * S_ + jb;
#pragma unroll
                for (int nt = 0; nt < 4; nt++) {
                    const int px = ng * 32 + nt * 8 + tg * 2;
                    uint32_t u = *(const uint32_t*)&g_xh[rowb + px];
                    __nv_bfloat162 bp = *(__nv_bfloat162*)&u;
                    float zx = lk(fmaf(__bfloat162float(bp.x), A0, B0)) + acc[mt][nt][r * 2] + bb;
                    float zy = lk(fmaf(__bfloat162float(bp.y), A0, B0)) + acc[mt][nt][r * 2 + 1] + bb;
                    *(uint32_t*)&g_zh[rowb + px] = packbf(zx, zy);
                    ps[mt][r] += zx + zy;
                    pq[mt][r] += zx * zx + zy * zy;
                }
            }
        }
    }

#pragma unroll
    for (int mt = 0; mt < 2; mt++)
#pragma unroll
        for (int r = 0; r < 2; r++) {
            ps[mt][r] += __shfl_xor_sync(0xffffffffu, ps[mt][r], 1);
            ps[mt][r] += __shfl_xor_sync(0xffffffffu, ps[mt][r], 2);
            pq[mt][r] += __shfl_xor_sync(0xffffffffu, pq[mt][r], 1);
            pq[mt][r] += __shfl_xor_sync(0xffffffffu, pq[mt][r], 2);
        }
    if ((lane & 3) == 0) {
#pragma unroll
        for (int mt = 0; mt < 2; mt++)
#pragma unroll
            for (int r = 0; r < 2; r++) {
                const int co = mg * 32 + mt * 16 + r * 8 + g;
                atomicAdd(&s_st[co], ps[mt][r]);
                atomicAdd(&s_st[64 + co], pq[mt][r]);
            }
    }
    __syncthreads();
    if (tid < 128) atomicAdd(&g_sum1[tid], s_st[tid]);
}

// ---------------- spatial mean of leaky(bn1(z)), bf16 input ----------------
__global__ void __launch_bounds__(256) k_mean() {
    const int bid = blockIdx.x;
    const int c = (bid >> 3) & 63;
    const float A = g_coef1[c], Bv = g_coef1[64 + c];
    const uint32_t* p = (const uint32_t*)(g_zh + (size_t)bid * S_);
    float s = 0.f;
    for (int i = threadIdx.x; i < S_ / 2; i += 256) {
        uint32_t u = p[i];
        __nv_bfloat162 bp = *(__nv_bfloat162*)&u;
        s += lk(fmaf(__bfloat162float(bp.x), A, Bv));
        s += lk(fmaf(__bfloat162float(bp.y), A, Bv));
    }
#pragma unroll
    for (int off = 16; off; off >>= 1) s += __shfl_down_sync(0xffffffffu, s, off);
    __shared__ float wa[8];
    const int lane = threadIdx.x & 31, wid = threadIdx.x >> 5;
    if (lane == 0) wa[wid] = s;
    __syncthreads();
    if (threadIdx.x == 0) {
        float ts = 0.f;
#pragma unroll
        for (int i = 0; i < 8; i++) ts += wa[i];
        g_m[bid] = ts * (1.0f / (float)S_);
    }
}

// ---------------- per-(b,t) 5x5 kernels ----------------
__global__ void k_kern(const float* __restrict__ w1, const float* __restrict__ b1) {
    const int idx = blockIdx.x * 256 + threadIdx.x;
    if (idx >= B_ * T_ * 25) return;
    const int b = idx / (T_ * 25);
    const int r = idx - b * (T_ * 25);
    const int t = r / 25;
    const int o = r - t * 25;
    float a = b1[o];
#pragma unroll 8
    for (int c = 0; c < 64; c++)
        a = fmaf(g_m[(b * C_ + c) * T_ + t], w1[o * 64 + c], a);
    g_kern[(b * T_ + t) * 25 + o] = a;
}

// ---------------- dynamic depthwise 5x5 conv ----------------
__global__ void __launch_bounds__(256) k_dynconv(const float* __restrict__ h,
                                                 float* __restrict__ out) {
    __shared__ float sp[100 * 100];
    __shared__ float sk[25];
    const int bid = blockIdx.x;
    const int b = bid >> 9;
    const int t = bid & 7;
    const int tid = threadIdx.x;
    const float* base = h + (size_t)bid * S_;

    for (int i = tid; i < 10000; i += 256) sp[i] = 0.f;
    if (tid < 25) sk[tid] = g_kern[(b * T_ + t) * 25 + tid];
    __syncthreads();
    for (int i = tid; i < S_; i += 256) {
        const int r = i / 96, col = i - r * 96;
        sp[(r + 2) * 100 + col + 2] = base[i];
    }
    __syncthreads();

    float kr[25];
#pragma unroll
    for (int q = 0; q < 25; q++) kr[q] = sk[q];

    float* ob = out + (size_t)bid * S_;
    for (int i = tid; i < S_; i += 256) {
        const int r = i / 96, col = i - r * 96;
        const float* pp = &sp[r * 100 + col];
        float a = 0.f;
#pragma unroll
        for (int ii = 0; ii < 5; ii++)
#pragma unroll
            for (int jj = 0; jj < 5; jj++)
                a = fmaf(pp[ii * 100 + jj], kr[ii * 5 + jj], a);
        ob[i] = a;
    }
}

// ---------------- launch ----------------
extern "C" void kernel_launch(void* const* d_in, const int* in_sizes, int n_in,
                              void* d_out, int out_size) {
    const float* h       = (const float*)d_in[0];
    const float* conv0_w = (const float*)d_in[1];
    const float* conv0_b = (const float*)d_in[2];
    const float* bn0_g   = (const float*)d_in[3];
    const float* bn0_b   = (const float*)d_in[4];
    const float* bn1_g   = (const float*)d_in[5];
    const float* bn1_b   = (const float*)d_in[6];
    const float* inW     = (const float*)d_in[7];
    const float* inB     = (const float*)d_in[8];
    const float* outW    = (const float*)d_in[9];
    const float* outB    = (const float*)d_in[10];
    const float* c1w     = (const float*)d_in[11];
    const float* c1b     = (const float*)d_in[12];
    float* out = (float*)d_out;

    cudaFuncSetAttribute(k_conv0_mma, cudaFuncAttributeMaxDynamicSharedMemorySize,
                         SM_CONV_TOT);
    cudaFuncSetAttribute(k_attn_fused, cudaFuncAttributeMaxDynamicSharedMemorySize,
                         SM_ATTN_TOT);

    k_prep<<<144, 256>>>(conv0_w, inW, outW);
    k_conv0_mma<<<dim3(4, B_ * T_), 512, SM_CONV_TOT>>>(h, conv0_b);
    k_coef<<<1, 64>>>(0, bn0_g, bn0_b);
    k_qkv_mma<<<dim3(S_ / 128, B_ * T_), 256>>>(inB);
    k_attn_fused<<<N_ / 128, 256, SM_ATTN_TOT>>>(outB);
    k_coef<<<1, 64>>>(1, bn1_g, bn1_b);
    k_mean<<<B_ * C_ * T_, 256>>>();
    k_kern<<<4, 256>>>(c1w, c1b);
    k_dynconv<<<B_ * C_ * T_, 256>>>(h, out);
}

// round 11
// speedup vs baseline: 1.2425x; 1.2182x over previous
#include <cuda_runtime.h>
#include <cuda_bf16.h>
#include <cstdint>

// Problem constants
#define B_ 4
#define C_ 64
#define T_ 8
#define X_ 96
#define Y_ 96
#define S_ 9216            // X_*Y_
#define N_ 36864           // B_*S_
#define TS_ 73728          // T_*S_
#define TOTAL_ 18874368    // B_*C_*T_*S_
#define QSZ_ 18874368      // T_*C_*N_
#define CNT_ 294912.0f     // B_*T_*S_

// -------- scratch (device globals; no runtime allocation) --------
__device__ __nv_bfloat16 g_xh[TOTAL_];            // conv0 raw output (pre-BN0), bf16
__device__ __nv_bfloat16 g_qkvh[3 * QSZ_];        // q,k,v bf16, [z][t][c][n]
__device__ __nv_bfloat16 g_zh[TOTAL_];            // residual + out_proj (pre-BN1), bf16
__device__ float g_sum0[128];
__device__ float g_sum1[128];
__device__ float g_coef0[128];                    // bn0: A[0:64], B[64:128]
__device__ float g_coef1[128];
__device__ float g_m[B_ * C_ * T_];
__device__ float g_kern[B_ * T_ * 25];
__device__ __align__(16) __nv_bfloat16 g_wk[64 * 576];   // conv0 [co][k], k=tap*64+ci
__device__ __align__(16) __nv_bfloat16 g_wqkv[192 * 64]; // in_proj bf16
__device__ __align__(16) __nv_bfloat16 g_wout[64 * 64];  // out_proj bf16

__device__ __forceinline__ float lk(float v) { return v >= 0.f ? v : 0.01f * v; }

__device__ __forceinline__ void mma_bf16(float* c, uint32_t a0, uint32_t a1,
                                         uint32_t a2, uint32_t a3,
                                         uint32_t b0, uint32_t b1) {
    asm volatile(
        "mma.sync.aligned.m16n8k16.row.col.f32.bf16.bf16.f32 "
        "{%0,%1,%2,%3}, {%4,%5,%6,%7}, {%8,%9}, {%0,%1,%2,%3};"
        : "+f"(c[0]), "+f"(c[1]), "+f"(c[2]), "+f"(c[3])
        : "r"(a0), "r"(a1), "r"(a2), "r"(a3), "r"(b0), "r"(b1));
}

__device__ __forceinline__ uint32_t packbf(float a, float b) {
    __nv_bfloat162 p = __floats2bfloat162_rn(a, b);
    return *(uint32_t*)&p;
}

__device__ __forceinline__ uint32_t smem_u32(const void* p) {
    uint32_t a;
    asm("{ .reg .u64 t; cvta.to.shared.u64 t, %1; cvt.u32.u64 %0, t; }" : "=r"(a) : "l"(p));
    return a;
}

__device__ __forceinline__ void ldsm_x4(uint32_t* r, uint32_t addr) {
    asm volatile("ldmatrix.sync.aligned.m8n8.x4.shared.b16 {%0,%1,%2,%3}, [%4];"
        : "=r"(r[0]), "=r"(r[1]), "=r"(r[2]), "=r"(r[3]) : "r"(addr));
}
__device__ __forceinline__ void ldsm_x4_t(uint32_t* r, uint32_t addr) {
    asm volatile("ldmatrix.sync.aligned.m8n8.x4.trans.shared.b16 {%0,%1,%2,%3}, [%4];"
        : "=r"(r[0]), "=r"(r[1]), "=r"(r[2]), "=r"(r[3]) : "r"(addr));
}

// ===================== combined prep (zero + all weight converts) =====================
__global__ void k_prep(const float* __restrict__ w, const float* __restrict__ inW,
                       const float* __restrict__ outW) {
    int i = blockIdx.x * 256 + threadIdx.x;
    if (i < 128) { g_sum0[i] = 0.f; g_sum1[i] = 0.f; }
    if (i < 64 * 576) {
        int co = i / 576, k = i - co * 576;
        g_wk[i] = __float2bfloat16(w[(co * 64 + (k & 63)) * 9 + (k >> 6)]);
    }
    if (i < 192 * 64) g_wqkv[i] = __float2bfloat16(inW[i]);
    if (i < 64 * 64) g_wout[i] = __float2bfloat16(outW[i]);
}

// ===================== conv0: persistent bf16 mma + ldmatrix, 512 thr =====================
#define SINW 72
#define ROWE (98 * SINW)                // 7056 elems per row slot
#define RING 8
#define WKS 584
#define SM_WK_OFF (RING * ROWE * 2)     // 112896 bytes
#define SM_CONV_TOT (SM_WK_OFF + 64 * WKS * 2)   // 187648 bytes

__device__ __forceinline__ void stage_row(__nv_bfloat16* sin_s, const float* hb,
                                          int gx, int tid) {
    const int slot = (gx + 8) & 7;
    __nv_bfloat16* dst = sin_s + slot * ROWE;
    if ((unsigned)gx >= 96u) {
        for (int e = tid; e < 6144; e += 512) {
            int ci = e / 96, y = e - ci * 96;
            dst[(y + 1) * SINW + ci] = __float2bfloat16(0.f);
        }
    } else {
        const float* hp = hb + (size_t)gx * 96;
        for (int e = tid; e < 6144; e += 512) {
            int ci = e / 96, y = e - ci * 96;
            dst[(y + 1) * SINW + ci] = __float2bfloat16(hp[(size_t)ci * TS_ + y]);
        }
    }
    if (tid < 64) dst[tid] = __float2bfloat16(0.f);
    else if (tid < 128) dst[97 * SINW + (tid - 64)] = __float2bfloat16(0.f);
}

__global__ void __launch_bounds__(512)
k_conv0_mma(const float* __restrict__ h, const float* __restrict__ bias) {
    extern __shared__ char smem[];
    __nv_bfloat16* sin_s = (__nv_bfloat16*)smem;
    __nv_bfloat16* wk_s = (__nv_bfloat16*)(smem + SM_WK_OFF);
    __shared__ float s_st[128];

    const int tid = threadIdx.x, lane = tid & 31, wid = tid >> 5;
    const int group = blockIdx.x, bt = blockIdx.y, b = bt >> 3, t = bt & 7;
    const float* hb = h + (size_t)b * (64 * TS_) + (size_t)t * S_;

    if (tid < 128) s_st[tid] = 0.f;
    {
        const uint4* src = (const uint4*)g_wk;
        for (int e = tid; e < 4608; e += 512) {
            int co = e / 72, q = e - co * 72;
            *(uint4*)&wk_s[co * WKS + q * 8] = src[e];
        }
    }
    {
        const int p0 = group * 2304;
        const int xlo = p0 / 96, xhi = (p0 + 255) / 96;
        for (int gx = xlo - 1; gx <= xhi + 1; gx++) stage_row(sin_s, hb, gx, tid);
    }
    __syncthreads();

    const int mg = wid >> 1, nh = wid & 1;
    const int g = lane >> 2, tg = lane & 3;

    const uint32_t sin_b = smem_u32(sin_s);
    const uint32_t wk_b = smem_u32(wk_s);

    uint32_t wkaddr[2];
    {
        const int koff = ((lane >> 3) & 1) * 8;
        const int cosub = (lane & 7) + ((lane >> 4) & 1) * 8;
#pragma unroll
        for (int ntp = 0; ntp < 2; ntp++) {
            const int co = nh * 32 + ntp * 16 + cosub;
            wkaddr[ntp] = wk_b + (uint32_t)(co * WKS + koff) * 2;
        }
    }
    const uint32_t khiA = (uint32_t)((lane >> 4) * 16);

    float bv[4][2];
#pragma unroll
    for (int nt = 0; nt < 4; nt++) {
        const int co0 = nh * 32 + nt * 8 + tg * 2;
        bv[nt][0] = __ldg(&bias[co0]);
        bv[nt][1] = __ldg(&bias[co0 + 1]);
    }

    float st_s[8], st_q[8];
#pragma unroll
    for (int i = 0; i < 8; i++) { st_s[i] = 0.f; st_q[i] = 0.f; }

    __nv_bfloat16* obB = g_xh + (size_t)b * (64 * TS_) + (size_t)t * S_;

    for (int ti = 0; ti < 9; ti++) {
        const int p0 = group * 2304 + ti * 256;
        const int xhi = (p0 + 255) / 96;
        if (ti < 8) {
            const int xhin = (p0 + 511) / 96;
            for (int gx = xhi + 2; gx <= xhin + 1; gx++) stage_row(sin_s, hb, gx, tid);
        }

        uint32_t aRB[2][3];
        {
            const int plbase = p0 + mg * 32 + (lane & 15);
#pragma unroll
            for (int mt = 0; mt < 2; mt++) {
                const int pl = plbase + mt * 16;
                const int px = pl / 96, py = pl - px * 96;
#pragma unroll
                for (int dx = 0; dx < 3; dx++)
                    aRB[mt][dx] = sin_b +
                        (uint32_t)(((px + dx + 7) & 7) * ROWE + py * SINW) * 2 + khiA;
            }
        }

        float acc[2][4][4];
#pragma unroll
        for (int mt = 0; mt < 2; mt++)
#pragma unroll
            for (int nt = 0; nt < 4; nt++)
#pragma unroll
                for (int i = 0; i < 4; i++) acc[mt][nt][i] = 0.f;

#pragma unroll
        for (int tap = 0; tap < 9; tap++) {
            const int dx = tap / 3, dy = tap - dx * 3;
            const uint32_t dyoff = (uint32_t)(dy * SINW) * 2;
#pragma unroll
            for (int kk = 0; kk < 4; kk++) {
                const uint32_t ko2 = (uint32_t)kk * 32;
                uint32_t A0[4], A1[4], Bf0[4], Bf1[4];
                ldsm_x4(A0, aRB[0][dx] + dyoff + ko2);
                ldsm_x4(A1, aRB[1][dx] + dyoff + ko2);
                const uint32_t bk = (uint32_t)(tap * 64 + kk * 16) * 2;
                ldsm_x4(Bf0, wkaddr[0] + bk);
                ldsm_x4(Bf1, wkaddr[1] + bk);
                mma_bf16(acc[0][0], A0[0], A0[1], A0[2], A0[3], Bf0[0], Bf0[1]);
                mma_bf16(acc[1][0], A1[0], A1[1], A1[2], A1[3], Bf0[0], Bf0[1]);
                mma_bf16(acc[0][1], A0[0], A0[1], A0[2], A0[3], Bf0[2], Bf0[3]);
                mma_bf16(acc[1][1], A1[0], A1[1], A1[2], A1[3], Bf0[2], Bf0[3]);
                mma_bf16(acc[0][2], A0[0], A0[1], A0[2], A0[3], Bf1[0], Bf1[1]);
                mma_bf16(acc[1][2], A1[0], A1[1], A1[2], A1[3], Bf1[0], Bf1[1]);
                mma_bf16(acc[0][3], A0[0], A0[1], A0[2], A0[3], Bf1[2], Bf1[3]);
                mma_bf16(acc[1][3], A1[0], A1[1], A1[2], A1[3], Bf1[2], Bf1[3]);
            }
        }

        __nv_bfloat16* ob = obB + p0;
#pragma unroll
        for (int nt = 0; nt < 4; nt++) {
            const int co0 = nh * 32 + nt * 8 + tg * 2;
#pragma unroll
            for (int mt = 0; mt < 2; mt++) {
                const int pr = mg * 32 + mt * 16 + g;
                float v0 = acc[mt][nt][0] + bv[nt][0];
                float v1 = acc[mt][nt][1] + bv[nt][1];
                float v2 = acc[mt][nt][2] + bv[nt][0];
                float v3 = acc[mt][nt][3] + bv[nt][1];
                ob[(size_t)co0 * TS_ + pr]           = __float2bfloat16(v0);
                ob[(size_t)(co0 + 1) * TS_ + pr]     = __float2bfloat16(v1);
                ob[(size_t)co0 * TS_ + pr + 8]       = __float2bfloat16(v2);
                ob[(size_t)(co0 + 1) * TS_ + pr + 8] = __float2bfloat16(v3);
                st_s[nt * 2]     += v0 + v2;
                st_q[nt * 2]     += v0 * v0 + v2 * v2;
                st_s[nt * 2 + 1] += v1 + v3;
                st_q[nt * 2 + 1] += v1 * v1 + v3 * v3;
            }
        }
        __syncthreads();
    }

#pragma unroll
    for (int i = 0; i < 8; i++) {
        st_s[i] += __shfl_xor_sync(0xffffffffu, st_s[i], 4);
        st_s[i] += __shfl_xor_sync(0xffffffffu, st_s[i], 8);
        st_s[i] += __shfl_xor_sync(0xffffffffu, st_s[i], 16);
        st_q[i] += __shfl_xor_sync(0xffffffffu, st_q[i], 4);
        st_q[i] += __shfl_xor_sync(0xffffffffu, st_q[i], 8);
        st_q[i] += __shfl_xor_sync(0xffffffffu, st_q[i], 16);
    }
    if (lane < 4) {
#pragma unroll
        for (int nt = 0; nt < 4; nt++)
#pragma unroll
            for (int r = 0; r < 2; r++) {
                const int co = nh * 32 + nt * 8 + lane * 2 + r;
                atomicAdd(&s_st[co], st_s[nt * 2 + r]);
                atomicAdd(&s_st[64 + co], st_q[nt * 2 + r]);
            }
    }
    __syncthreads();
    if (tid < 128) atomicAdd(&g_sum0[tid], s_st[tid]);
}

// ---------------- BN coefficients ----------------
__global__ void k_coef(int mode, const float* __restrict__ g,
                       const float* __restrict__ beta) {
    const int c = threadIdx.x;
    if (c >= 64) return;
    const float* sums = mode ? g_sum1 : g_sum0;
    float* coef = mode ? g_coef1 : g_coef0;
    const float inv = 1.0f / CNT_;
    float mu = sums[c] * inv;
    float var = sums[64 + c] * inv - mu * mu;
    float A = g[c] * rsqrtf(var + 1e-5f);
    coef[c] = A;
    coef[64 + c] = beta[c] - mu * A;
}

// ---------------- qkv: persistent bf16 mma, 512 thr, double-buffered Xt ----------------
#define QSM_WS (2 * 128 * 72 * 2)            // 36864: two Xt buffers [128][72]
#define QSM_TOT (QSM_WS + 192 * 72 * 2)      // 64512

__global__ void __launch_bounds__(512) k_qkv_mma(const float* __restrict__ bias) {
    extern __shared__ char smem[];
    __nv_bfloat16* Xt = (__nv_bfloat16*)smem;
    __nv_bfloat16* Ws = (__nv_bfloat16*)(smem + QSM_WS);
    const int tid = threadIdx.x, lane = tid & 31, wid = tid >> 5;
    const int group = blockIdx.x;
    const int bt = blockIdx.y, b = bt >> 3, t = bt & 7;

    // stage W once: [192][64] -> [192][72]
    {
        const uint4* src = (const uint4*)g_wqkv;
        for (int e = tid; e < 1536; e += 512) {
            int co = e >> 3, q = e & 7;
            *(uint4*)&Ws[co * 72 + q * 8] = src[e];
        }
    }
    const __nv_bfloat16* xbase = g_xh + ((size_t)(b * C_) * T_ + t) * S_;
    // stage tile 0 into buf 0 (bn0+leaky fused)
    {
        const __nv_bfloat16* xb = xbase + group * 18 * 128;
        for (int e = tid; e < 4096; e += 512) {
            int kp = e >> 7, n = e & 127;
            int k0 = kp * 2;
            float x0 = __bfloat162float(xb[(size_t)k0 * TS_ + n]);
            float x1 = __bfloat162float(xb[(size_t)(k0 + 1) * TS_ + n]);
            *(uint32_t*)&Xt[n * 72 + k0] =
                packbf(lk(fmaf(x0, g_coef0[k0], g_coef0[64 + k0])),
                       lk(fmaf(x1, g_coef0[k0 + 1], g_coef0[64 + k0 + 1])));
        }
    }
    __syncthreads();

    const int mg = wid >> 2, ng = wid & 3;   // mg: 48 co rows; ng: 32 pixels
    const int g = lane >> 2, tg = lane & 3;
    const uint32_t ws_b = smem_u32(Ws), xt_b = smem_u32(Xt);
    const uint32_t aAddr = ws_b +
        (uint32_t)((mg * 48 + (lane & 15)) * 72 + (lane >> 4) * 8) * 2;
    const int nsub = (lane & 7) + ((lane >> 4) & 1) * 8;
    const int koff = ((lane >> 3) & 1) * 8;
    const uint32_t bAddrBase = (uint32_t)((ng * 32 + nsub) * 72 + koff) * 2;

    float bb[3][2];
#pragma unroll
    for (int mt = 0; mt < 3; mt++) {
        const int co = mg * 48 + mt * 16 + g;
        bb[mt][0] = __ldg(&bias[co]);
        bb[mt][1] = __ldg(&bias[co + 8]);
    }

    for (int ti = 0; ti < 18; ti++) {
        const int j0 = (group * 18 + ti) * 128;
        const uint32_t xtb = xt_b + (uint32_t)(ti & 1) * (128 * 72 * 2);
        // stage next tile into the other buffer (consumed last iter; safe)
        if (ti < 17) {
            __nv_bfloat16* XtN = Xt + ((ti + 1) & 1) * (128 * 72);
            const __nv_bfloat16* xb = xbase + j0 + 128;
            for (int e = tid; e < 4096; e += 512) {
                int kp = e >> 7, n = e & 127;
                int k0 = kp * 2;
                float x0 = __bfloat162float(xb[(size_t)k0 * TS_ + n]);
                float x1 = __bfloat162float(xb[(size_t)(k0 + 1) * TS_ + n]);
                *(uint32_t*)&XtN[n * 72 + k0] =
                    packbf(lk(fmaf(x0, g_coef0[k0], g_coef0[64 + k0])),
                           lk(fmaf(x1, g_coef0[k0 + 1], g_coef0[64 + k0 + 1])));
            }
        }

        float acc[3][4][4];
#pragma unroll
        for (int mt = 0; mt < 3; mt++)
#pragma unroll
            for (int nt = 0; nt < 4; nt++)
#pragma unroll
                for (int i = 0; i < 4; i++) acc[mt][nt][i] = 0.f;

#pragma unroll
        for (int kk = 0; kk < 4; kk++) {
            const uint32_t ko2 = (uint32_t)kk * 32;
            uint32_t Af0[4], Af1[4], Af2[4], Bf0[4], Bf1[4];
            ldsm_x4(Af0, aAddr + ko2);
            ldsm_x4(Af1, aAddr + 16 * 72 * 2 + ko2);
            ldsm_x4(Af2, aAddr + 32 * 72 * 2 + ko2);
            ldsm_x4(Bf0, xtb + bAddrBase + ko2);
            ldsm_x4(Bf1, xtb + bAddrBase + 16 * 72 * 2 + ko2);
            mma_bf16(acc[0][0], Af0[0], Af0[1], Af0[2], Af0[3], Bf0[0], Bf0[1]);
            mma_bf16(acc[1][0], Af1[0], Af1[1], Af1[2], Af1[3], Bf0[0], Bf0[1]);
            mma_bf16(acc[2][0], Af2[0], Af2[1], Af2[2], Af2[3], Bf0[0], Bf0[1]);
            mma_bf16(acc[0][1], Af0[0], Af0[1], Af0[2], Af0[3], Bf0[2], Bf0[3]);
            mma_bf16(acc[1][1], Af1[0], Af1[1], Af1[2], Af1[3], Bf0[2], Bf0[3]);
            mma_bf16(acc[2][1], Af2[0], Af2[1], Af2[2], Af2[3], Bf0[2], Bf0[3]);
            mma_bf16(acc[0][2], Af0[0], Af0[1], Af0[2], Af0[3], Bf1[0], Bf1[1]);
            mma_bf16(acc[1][2], Af1[0], Af1[1], Af1[2], Af1[3], Bf1[0], Bf1[1]);
            mma_bf16(acc[2][2], Af2[0], Af2[1], Af2[2], Af2[3], Bf1[0], Bf1[1]);
            mma_bf16(acc[0][3], Af0[0], Af0[1], Af0[2], Af0[3], Bf1[2], Bf1[3]);
            mma_bf16(acc[1][3], Af1[0], Af1[1], Af1[2], Af1[3], Bf1[2], Bf1[3]);
            mma_bf16(acc[2][3], Af2[0], Af2[1], Af2[2], Af2[3], Bf1[2], Bf1[3]);
        }

        // writeout: co rows -> [z][t][mo][n], packed bf16x2
        const int ncol = b * S_ + j0 + ng * 32 + tg * 2;
#pragma unroll
        for (int mt = 0; mt < 3; mt++) {
#pragma unroll
            for (int r = 0; r < 2; r++) {
                const int co = mg * 48 + mt * 16 + r * 8 + g;
                const int z = co >> 6, mo = co & 63;
                const float bvv = bb[mt][r];
                __nv_bfloat16* op = g_qkvh + (size_t)z * QSZ_ +
                                    (size_t)(t * 64 + mo) * N_ + ncol;
#pragma unroll
                for (int nt = 0; nt < 4; nt++) {
                    *(uint32_t*)&op[nt * 8] =
                        packbf(acc[mt][nt][r * 2] + bvv, acc[mt][nt][r * 2 + 1] + bvv);
                }
            }
        }
        __syncthreads();
    }
}

// ---------------- fused attention + out_proj + residual + BN1 stats ----------------
#define OTP 136
#define SM_WS_OFF (8 * 64 * OTP * 2)                 // 139264
#define SM_ATTN_TOT (SM_WS_OFF + 64 * 72 * 2)        // 148480

__global__ void __launch_bounds__(256)
k_attn_fused(const float* __restrict__ bias) {
    extern __shared__ char smem[];
    __nv_bfloat16* Ot = (__nv_bfloat16*)smem;             // [t][c][OTP]
    __nv_bfloat16* Ws = (__nv_bfloat16*)(smem + SM_WS_OFF);
    __shared__ float s_st[128];
    const int tid = threadIdx.x, lane = tid & 31, wid = tid >> 5;
    const int j0 = blockIdx.x * 128;
    const int b = j0 / S_;
    const int jb = j0 - b * S_;

    if (tid < 128) s_st[tid] = 0.f;
    {
        const uint4* src = (const uint4*)g_wout;
        for (int e = tid; e < 512; e += 256) {
            int co = e >> 3, q = e & 7;
            *(uint4*)&Ws[co * 72 + q * 8] = src[e];
        }
    }

    // ---- phase 1: attention for 128 n x 8 heads (4 heads per thread) ----
    {
        const int nl = tid & 127;
        const int hp = tid >> 7;
        const int n = j0 + nl;
        const __nv_bfloat16* qp = g_qkvh;
        const __nv_bfloat16* kp = g_qkvh + QSZ_;
        const __nv_bfloat16* vp = g_qkvh + 2 * (size_t)QSZ_;
        const float scale = 0.3535533905932738f;
        for (int i = 0; i < 4; i++) {
            const int cb = (hp * 4 + i) * 8;
            float kk[8][8], vv[8][8];
#pragma unroll
            for (int tt = 0; tt < 8; tt++)
#pragma unroll
                for (int d = 0; d < 8; d++) {
                    const size_t idx = (size_t)(tt * 64 + cb + d) * N_ + n;
                    kk[tt][d] = __bfloat162float(kp[idx]);
                    vv[tt][d] = __bfloat162float(vp[idx]);
                }
#pragma unroll
            for (int tq = 0; tq < 8; tq++) {
                float q[8];
#pragma unroll
                for (int d = 0; d < 8; d++)
                    q[d] = __bfloat162float(qp[(size_t)(tq * 64 + cb + d) * N_ + n]) * scale;
                float s[8];
                float mx = -1e30f;
#pragma unroll
                for (int tt = 0; tt < 8; tt++) {
                    float a = 0.f;
#pragma unroll
                    for (int d = 0; d < 8; d++) a = fmaf(q[d], kk[tt][d], a);
                    s[tt] = a;
                    mx = fmaxf(mx, a);
                }
                float sum = 0.f;
#pragma unroll
                for (int tt = 0; tt < 8; tt++) { s[tt] = __expf(s[tt] - mx); sum += s[tt]; }
                const float inv = 1.0f / sum;
#pragma unroll
                for (int d = 0; d < 8; d++) {
                    float o = 0.f;
#pragma unroll
                    for (int tt = 0; tt < 8; tt++) o = fmaf(s[tt], vv[tt][d], o);
                    Ot[(tq * 64 + cb + d) * OTP + nl] = __float2bfloat16(o * inv);
                }
            }
        }
    }
    __syncthreads();

    // ---- phase 2: out_proj per t + residual + z write + BN1 stats ----
    const int mg = wid >> 2, ng = wid & 3;
    const int g = lane >> 2, tg = lane & 3;
    const uint32_t ws_b = smem_u32(Ws);
    const uint32_t ot_b = smem_u32(Ot);
    const uint32_t aAddr0 = ws_b + (uint32_t)((mg * 32 + (lane & 15)) * 72 + (lane >> 4) * 8) * 2;
    const int krow_l = (lane & 7) + ((lane >> 3) & 1) * 8;
    const int np_l = ng * 32 + ((lane >> 4) & 1) * 8;

    float ps[2][2], pq[2][2];
#pragma unroll
    for (int mt = 0; mt < 2; mt++)
#pragma unroll
        for (int r = 0; r < 2; r++) { ps[mt][r] = 0.f; pq[mt][r] = 0.f; }

    for (int t = 0; t < 8; t++) {
        float acc[2][4][4];
#pragma unroll
        for (int mt = 0; mt < 2; mt++)
#pragma unroll
            for (int nt = 0; nt < 4; nt++)
#pragma unroll
                for (int i = 0; i < 4; i++) acc[mt][nt][i] = 0.f;

#pragma unroll
        for (int kk = 0; kk < 4; kk++) {
            uint32_t Af0[4], Af1[4], Bf0[4], Bf1[4];
            ldsm_x4(Af0, aAddr0 + (uint32_t)kk * 32);
            ldsm_x4(Af1, aAddr0 + 16 * 72 * 2 + (uint32_t)kk * 32);
            const uint32_t base =
                ot_b + (uint32_t)((t * 64 + kk * 16 + krow_l) * OTP + np_l) * 2;
            ldsm_x4_t(Bf0, base);
            ldsm_x4_t(Bf1, base + 32);   // +16 n elems
            mma_bf16(acc[0][0], Af0[0], Af0[1], Af0[2], Af0[3], Bf0[0], Bf0[1]);
            mma_bf16(acc[1][0], Af1[0], Af1[1], Af1[2], Af1[3], Bf0[0], Bf0[1]);
            mma_bf16(acc[0][1], Af0[0], Af0[1], Af0[2], Af0[3], Bf0[2], Bf0[3]);
            mma_bf16(acc[1][1], Af1[0], Af1[1], Af1[2], Af1[3], Bf0[2], Bf0[3]);
            mma_bf16(acc[0][2], Af0[0], Af0[1], Af0[2], Af0[3], Bf1[0], Bf1[1]);
            mma_bf16(acc[1][2], Af1[0], Af1[1], Af1[2], Af1[3], Bf1[0], Bf1[1]);
            mma_bf16(acc[0][3], Af0[0], Af0[1], Af0[2], Af0[3], Bf1[2], Bf1[3]);
            mma_bf16(acc[1][3], Af1[0], Af1[1], Af1[2], Af1[3], Bf1[2], Bf1[3]);
        }

#pragma unroll
        for (int mt = 0; mt < 2; mt++) {
#pragma unroll
            for (int r = 0; r < 2; r++) {
                const int co = mg * 32 + mt * 16 + r * 8 + g;
                const float bb = __ldg(&bias[co]);
                const float A0 = g_coef0[co], B0 = g_coef0[64 + co];
                const size_t rowb = ((size_t)(b * C_ + co) * T_ + t) * S_ + jb;
#pragma unroll
                for (int nt = 0; nt < 4; nt++) {
                    const int px = ng * 32 + nt * 8 + tg * 2;
                    uint32_t u = *(const uint32_t*)&g_xh[rowb + px];
                    __nv_bfloat162 bp = *(__nv_bfloat162*)&u;
                    float zx = lk(fmaf(__bfloat162float(bp.x), A0, B0)) + acc[mt][nt][r * 2] + bb;
                    float zy = lk(fmaf(__bfloat162float(bp.y), A0, B0)) + acc[mt][nt][r * 2 + 1] + bb;
                    *(uint32_t*)&g_zh[rowb + px] = packbf(zx, zy);
                    ps[mt][r] += zx + zy;
                    pq[mt][r] += zx * zx + zy * zy;
                }
            }
        }
    }

#pragma unroll
    for (int mt = 0; mt < 2; mt++)
#pragma unroll
        for (int r = 0; r < 2; r++) {
            ps[mt][r] += __shfl_xor_sync(0xffffffffu, ps[mt][r], 1);
            ps[mt][r] += __shfl_xor_sync(0xffffffffu, ps[mt][r], 2);
            pq[mt][r] += __shfl_xor_sync(0xffffffffu, pq[mt][r], 1);
            pq[mt][r] += __shfl_xor_sync(0xffffffffu, pq[mt][r], 2);
        }
    if ((lane & 3) == 0) {
#pragma unroll
        for (int mt = 0; mt < 2; mt++)
#pragma unroll
            for (int r = 0; r < 2; r++) {
                const int co = mg * 32 + mt * 16 + r * 8 + g;
                atomicAdd(&s_st[co], ps[mt][r]);
                atomicAdd(&s_st[64 + co], pq[mt][r]);
            }
    }
    __syncthreads();
    if (tid < 128) atomicAdd(&g_sum1[tid], s_st[tid]);
}

// ---------------- spatial mean of leaky(bn1(z)), bf16 input ----------------
__global__ void __launch_bounds__(256) k_mean() {
    const int bid = blockIdx.x;
    const int c = (bid >> 3) & 63;
    const float A = g_coef1[c], Bv = g_coef1[64 + c];
    const uint32_t* p = (const uint32_t*)(g_zh + (size_t)bid * S_);
    float s = 0.f;
    for (int i = threadIdx.x; i < S_ / 2; i += 256) {
        uint32_t u = p[i];
        __nv_bfloat162 bp = *(__nv_bfloat162*)&u;
        s += lk(fmaf(__bfloat162float(bp.x), A, Bv));
        s += lk(fmaf(__bfloat162float(bp.y), A, Bv));
    }
#pragma unroll
    for (int off = 16; off; off >>= 1) s += __shfl_down_sync(0xffffffffu, s, off);
    __shared__ float wa[8];
    const int lane = threadIdx.x & 31, wid = threadIdx.x >> 5;
    if (lane == 0) wa[wid] = s;
    __syncthreads();
    if (threadIdx.x == 0) {
        float ts = 0.f;
#pragma unroll
        for (int i = 0; i < 8; i++) ts += wa[i];
        g_m[bid] = ts * (1.0f / (float)S_);
    }
}

// ---------------- per-(b,t) 5x5 kernels ----------------
__global__ void k_kern(const float* __restrict__ w1, const float* __restrict__ b1) {
    const int idx = blockIdx.x * 256 + threadIdx.x;
    if (idx >= B_ * T_ * 25) return;
    const int b = idx / (T_ * 25);
    const int r = idx - b * (T_ * 25);
    const int t = r / 25;
    const int o = r - t * 25;
    float a = b1[o];
#pragma unroll 8
    for (int c = 0; c < 64; c++)
        a = fmaf(g_m[(b * C_ + c) * T_ + t], w1[o * 64 + c], a);
    g_kern[(b * T_ + t) * 25 + o] = a;
}

// ---------------- dynamic depthwise 5x5 conv ----------------
__global__ void __launch_bounds__(256) k_dynconv(const float* __restrict__ h,
                                                 float* __restrict__ out) {
    __shared__ float sp[100 * 100];
    __shared__ float sk[25];
    const int bid = blockIdx.x;
    const int b = bid >> 9;
    const int t = bid & 7;
    const int tid = threadIdx.x;
    const float* base = h + (size_t)bid * S_;

    for (int i = tid; i < 10000; i += 256) sp[i] = 0.f;
    if (tid < 25) sk[tid] = g_kern[(b * T_ + t) * 25 + tid];
    __syncthreads();
    for (int i = tid; i < S_; i += 256) {
        const int r = i / 96, col = i - r * 96;
        sp[(r + 2) * 100 + col + 2] = base[i];
    }
    __syncthreads();

    float kr[25];
#pragma unroll
    for (int q = 0; q < 25; q++) kr[q] = sk[q];

    float* ob = out + (size_t)bid * S_;
    for (int i = tid; i < S_; i += 256) {
        const int r = i / 96, col = i - r * 96;
        const float* pp = &sp[r * 100 + col];
        float a = 0.f;
#pragma unroll
        for (int ii = 0; ii < 5; ii++)
#pragma unroll
            for (int jj = 0; jj < 5; jj++)
                a = fmaf(pp[ii * 100 + jj], kr[ii * 5 + jj], a);
        ob[i] = a;
    }
}

// ---------------- launch ----------------
extern "C" void kernel_launch(void* const* d_in, const int* in_sizes, int n_in,
                              void* d_out, int out_size) {
    const float* h       = (const float*)d_in[0];
    const float* conv0_w = (const float*)d_in[1];
    const float* conv0_b = (const float*)d_in[2];
    const float* bn0_g   = (const float*)d_in[3];
    const float* bn0_b   = (const float*)d_in[4];
    const float* bn1_g   = (const float*)d_in[5];
    const float* bn1_b   = (const float*)d_in[6];
    const float* inW     = (const float*)d_in[7];
    const float* inB     = (const float*)d_in[8];
    const float* outW    = (const float*)d_in[9];
    const float* outB    = (const float*)d_in[10];
    const float* c1w     = (const float*)d_in[11];
    const float* c1b     = (const float*)d_in[12];
    float* out = (float*)d_out;

    cudaFuncSetAttribute(k_conv0_mma, cudaFuncAttributeMaxDynamicSharedMemorySize,
                         SM_CONV_TOT);
    cudaFuncSetAttribute(k_qkv_mma, cudaFuncAttributeMaxDynamicSharedMemorySize,
                         QSM_TOT);
    cudaFuncSetAttribute(k_attn_fused, cudaFuncAttributeMaxDynamicSharedMemorySize,
                         SM_ATTN_TOT);

    k_prep<<<144, 256>>>(conv0_w, inW, outW);
    k_conv0_mma<<<dim3(4, B_ * T_), 512, SM_CONV_TOT>>>(h, conv0_b);
    k_coef<<<1, 64>>>(0, bn0_g, bn0_b);
    k_qkv_mma<<<dim3(4, B_ * T_), 512, QSM_TOT>>>(inB);
    k_attn_fused<<<N_ / 128, 256, SM_ATTN_TOT>>>(outB);
    k_coef<<<1, 64>>>(1, bn1_g, bn1_b);
    k_mean<<<B_ * C_ * T_, 256>>>();
    k_kern<<<4, 256>>>(c1w, c1b);
    k_dynconv<<<B_ * C_ * T_, 256>>>(h, out);
}